// round 14
// baseline (speedup 1.0000x reference)
#include <cuda_runtime.h>
#include <cuda_bf16.h>
#include <math.h>
#include <stdint.h>

// Problem constants
#define NND 50000
#define FF  256
#define HH  128
#define EE  800000
#define BB  64
#define TT  50

// ---------------- device scratch ----------------
__device__ float g_reduced[NND * HH];
__device__ float g_agg[NND * HH];
__device__ float g_aggB[NND * HH];
__device__ float g_tmp[NND * HH];
__device__ float g_s[NND * HH];
__device__ float g_invdeg[NND];
__device__ int   g_deg[NND];
__device__ float g_ts[BB * TT * HH];
__device__ float g_gates[BB * TT * 4 * HH];
__device__ float g_h1[BB * TT * HH];
__device__ float g_h2[BB * TT * HH];
__device__ float g_qkv[BB * TT * 3 * HH];
__device__ float g_olast[BB * HH];
__device__ float g_WhhT0[HH * 4 * HH];   // [128][512] transposed fp32 Whh0
__device__ float g_WhhT1[HH * 4 * HH];   // [128][512] transposed fp32 Whh1

__device__ __forceinline__ float sigf(float x) { return 1.0f / (1.0f + __expf(-x)); }
// tanh(x) = 1 - 2/(exp(2x)+1)  -> MUFU.EX2 + MUFU.RCP
__device__ __forceinline__ float tanh_e(float x) { return 1.0f - 2.0f / (__expf(2.0f * x) + 1.0f); }

__device__ __forceinline__ uint32_t f2tf32(float f) {
    uint32_t u;
    asm("cvt.rna.tf32.f32 %0, %1;" : "=r"(u) : "f"(f));
    return u;
}

__device__ __forceinline__ void mma_tf32(float* d, const uint32_t* a, const uint32_t* b) {
    asm volatile("mma.sync.aligned.m16n8k8.row.col.f32.tf32.tf32.f32 "
                 "{%0,%1,%2,%3}, {%4,%5,%6,%7}, {%8,%9}, {%0,%1,%2,%3};"
                 : "+f"(d[0]), "+f"(d[1]), "+f"(d[2]), "+f"(d[3])
                 : "r"(a[0]), "r"(a[1]), "r"(a[2]), "r"(a[3]), "r"(b[0]), "r"(b[1]));
}

// ---------------- degree kernels ----------------
__global__ __launch_bounds__(256) void deg_kernel(const int* __restrict__ dst, int* __restrict__ deg, int E) {
    int i = blockIdx.x * blockDim.x + threadIdx.x;
    if (i < E) atomicAdd(&deg[dst[i]], 1);
}

__global__ __launch_bounds__(256) void invdeg_kernel(const int* __restrict__ deg, float* __restrict__ inv, int n) {
    int i = blockIdx.x * blockDim.x + threadIdx.x;
    if (i < n) inv[i] = 1.0f / (float)max(deg[i], 1);
}

// ---------------- weight transpose: Whh[512][128] -> WhhT[128][512], fp32 ----------------
__global__ __launch_bounds__(256) void transposeW_kernel(const float* __restrict__ W0,
                                                         const float* __restrict__ W1,
                                                         float* __restrict__ T0,
                                                         float* __restrict__ T1) {
    int idx = blockIdx.x * blockDim.x + threadIdx.x;
    if (idx < 512 * 128) {
        int j = idx >> 7;      // gate row 0..511
        int k = idx & 127;     // hidden col 0..127
        T0[k * 512 + j] = W0[idx];
        T1[k * 512 + j] = W1[idx];
    }
}

// ---------------- scatter-add (one warp per edge, v4 reductions) ----------------
__global__ __launch_bounds__(256) void scatter_add_kernel(const float* __restrict__ feat,
                                   const int* __restrict__ src,
                                   const int* __restrict__ dst,
                                   float* __restrict__ agg, int E) {
    int idx = blockIdx.x * blockDim.x + threadIdx.x;
    int e = idx >> 5;
    if (e >= E) return;
    int lane = idx & 31;
    int s = __ldg(src + e);
    int d = __ldg(dst + e);
    float4 v = *(const float4*)(feat + (size_t)s * HH + lane * 4);
    float* p = agg + (size_t)d * HH + lane * 4;
    asm volatile("red.global.add.v4.f32 [%0], {%1,%2,%3,%4};"
                 :: "l"(p), "f"(v.x), "f"(v.y), "f"(v.z), "f"(v.w) : "memory");
}

// ---------------- tf32 tensor-core NT GEMM (+ optional addend) ----------------
// C = A1@B1^T (+A2@B2^T) + bias + Cadd, optional relu, optional rowscale on A1 rows.
#define KT 16
__global__ __launch_bounds__(256) void gemm_tf32_kernel(
        const float* __restrict__ A1, const float* __restrict__ B1,
        const float* __restrict__ A2, const float* __restrict__ B2,
        const float* __restrict__ rowscale,
        const float* __restrict__ bias,
        const float* __restrict__ Cadd,
        float* __restrict__ C,
        int M, int N, int Ktot, int Ksplit, int relu) {
    __shared__ uint32_t As[2][KT][136];
    __shared__ uint32_t Bs[2][KT][136];
    const int tid  = threadIdx.x;
    const int m0   = blockIdx.x * 128;
    const int n0   = blockIdx.y * 128;
    const int warp = tid >> 5, lane = tid & 31;
    const int wm   = (warp >> 1) * 32;   // 4 warps in m
    const int wn   = (warp & 1) * 64;    // 2 warps in n
    const int g    = lane >> 2, c = lane & 3;
    const bool haveScale = (rowscale != nullptr);

    float acc[2][8][4];
#pragma unroll
    for (int mt = 0; mt < 2; mt++)
#pragma unroll
        for (int nt = 0; nt < 8; nt++)
#pragma unroll
            for (int r = 0; r < 4; r++) acc[mt][nt][r] = 0.0f;

    const int numSlabs = Ktot / KT;

    const int row0 = tid & 127, kc0 = tid >> 7;          // kc0 in {0,1}
    const int row1 = tid & 127, kc1 = (tid >> 7) + 2;    // {2,3}

    float4 pa[2], pb[2];

    auto loadSlab = [&](int s) {
        int kbase = s * KT;
        const float* A; const float* Bm; int lda, koff; bool sc;
        if (kbase < Ksplit) { A = A1; Bm = B1; lda = Ksplit;        koff = kbase;          sc = haveScale; }
        else                { A = A2; Bm = B2; lda = Ktot - Ksplit; koff = kbase - Ksplit; sc = false; }
        {
            int m = m0 + row0;
            pa[0] = make_float4(0.f, 0.f, 0.f, 0.f);
            if (m < M) {
                pa[0] = *(const float4*)(A + (size_t)m * lda + koff + kc0 * 4);
                if (sc) { float sv = rowscale[m]; pa[0].x *= sv; pa[0].y *= sv; pa[0].z *= sv; pa[0].w *= sv; }
            }
            pb[0] = *(const float4*)(Bm + (size_t)(n0 + row0) * lda + koff + kc0 * 4);
        }
        {
            int m = m0 + row1;
            pa[1] = make_float4(0.f, 0.f, 0.f, 0.f);
            if (m < M) {
                pa[1] = *(const float4*)(A + (size_t)m * lda + koff + kc1 * 4);
                if (sc) { float sv = rowscale[m]; pa[1].x *= sv; pa[1].y *= sv; pa[1].z *= sv; pa[1].w *= sv; }
            }
            pb[1] = *(const float4*)(Bm + (size_t)(n0 + row1) * lda + koff + kc1 * 4);
        }
    };

    auto storeSlab = [&](int buf) {
        int k0 = kc0 * 4;
        As[buf][k0 + 0][row0] = f2tf32(pa[0].x); As[buf][k0 + 1][row0] = f2tf32(pa[0].y);
        As[buf][k0 + 2][row0] = f2tf32(pa[0].z); As[buf][k0 + 3][row0] = f2tf32(pa[0].w);
        Bs[buf][k0 + 0][row0] = f2tf32(pb[0].x); Bs[buf][k0 + 1][row0] = f2tf32(pb[0].y);
        Bs[buf][k0 + 2][row0] = f2tf32(pb[0].z); Bs[buf][k0 + 3][row0] = f2tf32(pb[0].w);
        int k1 = kc1 * 4;
        As[buf][k1 + 0][row1] = f2tf32(pa[1].x); As[buf][k1 + 1][row1] = f2tf32(pa[1].y);
        As[buf][k1 + 2][row1] = f2tf32(pa[1].z); As[buf][k1 + 3][row1] = f2tf32(pa[1].w);
        Bs[buf][k1 + 0][row1] = f2tf32(pb[1].x); Bs[buf][k1 + 1][row1] = f2tf32(pb[1].y);
        Bs[buf][k1 + 2][row1] = f2tf32(pb[1].z); Bs[buf][k1 + 3][row1] = f2tf32(pb[1].w);
    };

    loadSlab(0);
    storeSlab(0);
    __syncthreads();

    for (int s = 0; s < numSlabs; s++) {
        int cur = s & 1;
        bool more = (s + 1) < numSlabs;
        if (more) loadSlab(s + 1);
#pragma unroll
        for (int k8 = 0; k8 < 2; k8++) {
            int kb = k8 * 8;
            uint32_t afr[2][4], bfr[8][2];
#pragma unroll
            for (int mt = 0; mt < 2; mt++) {
                int mb = wm + mt * 16 + g;
                afr[mt][0] = As[cur][kb + c][mb];
                afr[mt][1] = As[cur][kb + c][mb + 8];
                afr[mt][2] = As[cur][kb + c + 4][mb];
                afr[mt][3] = As[cur][kb + c + 4][mb + 8];
            }
#pragma unroll
            for (int nt = 0; nt < 8; nt++) {
                int nb = wn + nt * 8 + g;
                bfr[nt][0] = Bs[cur][kb + c][nb];
                bfr[nt][1] = Bs[cur][kb + c + 4][nb];
            }
#pragma unroll
            for (int mt = 0; mt < 2; mt++)
#pragma unroll
                for (int nt = 0; nt < 8; nt++)
                    mma_tf32(acc[mt][nt], afr[mt], bfr[nt]);
        }
        __syncthreads();
        if (more) {
            storeSlab(1 - cur);
            __syncthreads();
        }
    }

    // epilogue
#pragma unroll
    for (int mt = 0; mt < 2; mt++) {
#pragma unroll
        for (int nt = 0; nt < 8; nt++) {
            const float* d = acc[mt][nt];
            int mrow = m0 + wm + mt * 16 + g;
            int ncol = n0 + wn + nt * 8 + 2 * c;
            float b0v = 0.f, b1v = 0.f;
            if (bias) { b0v = bias[ncol]; b1v = bias[ncol + 1]; }
            float v0 = d[0] + b0v, v1 = d[1] + b1v;
            float v2 = d[2] + b0v, v3 = d[3] + b1v;
            if (Cadd) {
                if (mrow < M) {
                    float2 c0 = *(const float2*)(Cadd + (size_t)mrow * N + ncol);
                    v0 += c0.x; v1 += c0.y;
                }
                if (mrow + 8 < M) {
                    float2 c1 = *(const float2*)(Cadd + (size_t)(mrow + 8) * N + ncol);
                    v2 += c1.x; v3 += c1.y;
                }
            }
            if (relu) {
                v0 = fmaxf(v0, 0.f); v1 = fmaxf(v1, 0.f);
                v2 = fmaxf(v2, 0.f); v3 = fmaxf(v3, 0.f);
            }
            if (mrow < M)     *(float2*)(C + (size_t)mrow * N + ncol)       = make_float2(v0, v1);
            if (mrow + 8 < M) *(float2*)(C + (size_t)(mrow + 8) * N + ncol) = make_float2(v2, v3);
        }
    }
}

// ---------------- LSTM recurrence: fp32 smem weights, 4 independent accumulators ----------------
#define SW_K 112
#define KREM (HH - SW_K)   // 16
#define LSTM_SMEM (SW_K * 512 * 4 + HH * 4 + 4 * HH * 4)   // 231936 bytes
__global__ __launch_bounds__(512) void lstm_rec_kernel(
                                const float* __restrict__ gx,    // B*T*512 = x@Wih^T + bih
                                const float* __restrict__ WhhT,  // [128][512] fp32
                                const float* __restrict__ bhh,   // [512]
                                float* __restrict__ hout) {      // B*T*128
    extern __shared__ float smemf[];
    float* sw   = smemf;                  // [SW_K][512]
    float* sh_h = smemf + SW_K * 512;     // [128]
    float* sh_g = sh_h + HH;              // [512]
    const int b = blockIdx.x;
    const int j = threadIdx.x;            // 0..511

    for (int idx = j; idx < SW_K * 512; idx += 512) sw[idx] = WhhT[idx];
    const float bh = __ldg(bhh + j);
    float cstate = 0.0f;
    if (j < HH) sh_h[j] = 0.0f;
    __syncthreads();

    const float* gbase = gx + (size_t)b * TT * 512;
    const float* wrem_base = WhhT + SW_K * 512;
    for (int t = 0; t < TT; t++) {
        float wrem[KREM];
#pragma unroll
        for (int i = 0; i < KREM; i++)
            wrem[i] = __ldg(wrem_base + i * 512 + j);   // L2, prefetched (MLP=16)
        // 4 independent accumulators break the serial 448-cycle FMA chain
        float a0 = gbase[t * 512 + j] + bh, a1 = 0.f, a2 = 0.f, a3 = 0.f;
#pragma unroll
        for (int kc = 0; kc < SW_K; kc += 16) {
            const float4 h0 = *(const float4*)&sh_h[kc];
            const float4 h1 = *(const float4*)&sh_h[kc + 4];
            const float4 h2 = *(const float4*)&sh_h[kc + 8];
            const float4 h3 = *(const float4*)&sh_h[kc + 12];
            a0 += sw[(kc + 0) * 512 + j] * h0.x + sw[(kc + 1) * 512 + j] * h0.y
                + sw[(kc + 2) * 512 + j] * h0.z + sw[(kc + 3) * 512 + j] * h0.w;
            a1 += sw[(kc + 4) * 512 + j] * h1.x + sw[(kc + 5) * 512 + j] * h1.y
                + sw[(kc + 6) * 512 + j] * h1.z + sw[(kc + 7) * 512 + j] * h1.w;
            a2 += sw[(kc + 8) * 512 + j] * h2.x + sw[(kc + 9) * 512 + j] * h2.y
                + sw[(kc + 10) * 512 + j] * h2.z + sw[(kc + 11) * 512 + j] * h2.w;
            a3 += sw[(kc + 12) * 512 + j] * h3.x + sw[(kc + 13) * 512 + j] * h3.y
                + sw[(kc + 14) * 512 + j] * h3.z + sw[(kc + 15) * 512 + j] * h3.w;
        }
        {
            const float4 h0 = *(const float4*)&sh_h[SW_K];
            const float4 h1 = *(const float4*)&sh_h[SW_K + 4];
            const float4 h2 = *(const float4*)&sh_h[SW_K + 8];
            const float4 h3 = *(const float4*)&sh_h[SW_K + 12];
            a0 += wrem[0] * h0.x + wrem[1] * h0.y + wrem[2] * h0.z + wrem[3] * h0.w;
            a1 += wrem[4] * h1.x + wrem[5] * h1.y + wrem[6] * h1.z + wrem[7] * h1.w;
            a2 += wrem[8] * h2.x + wrem[9] * h2.y + wrem[10] * h2.z + wrem[11] * h2.w;
            a3 += wrem[12] * h3.x + wrem[13] * h3.y + wrem[14] * h3.z + wrem[15] * h3.w;
        }
        sh_g[j] = (a0 + a1) + (a2 + a3);
        __syncthreads();
        if (j < HH) {
            float gi = sh_g[j], gf = sh_g[HH + j], gg = sh_g[2 * HH + j], go = sh_g[3 * HH + j];
            cstate = sigf(gf) * cstate + sigf(gi) * tanh_e(gg);
            float h = sigf(go) * tanh_e(cstate);
            sh_h[j] = h;
            hout[((size_t)b * TT + t) * HH + j] = h;
        }
        __syncthreads();
    }
}

// ---------------- attention: only last query row needed ----------------
__global__ __launch_bounds__(256) void attn_last_kernel(const float* __restrict__ qkv, float* __restrict__ olast) {
    int gidx = blockIdx.x * blockDim.x + threadIdx.x;
    int w = gidx >> 5;                // 0..127 : (b, head)
    if (w >= BB * 2) return;
    int lane = threadIdx.x & 31;
    int wl = threadIdx.x >> 5;
    int b = w >> 1, h = w & 1;
    const float* base = qkv + (size_t)b * TT * 384;
    const float* q = base + 49 * 384 + h * 64;
    float q0 = q[lane], q1 = q[lane + 32];
    __shared__ float sc[8][TT];
    for (int j = 0; j < TT; j++) {
        const float* kp = base + j * 384 + 128 + h * 64;
        float p = q0 * kp[lane] + q1 * kp[lane + 32];
#pragma unroll
        for (int o = 16; o; o >>= 1) p += __shfl_down_sync(0xffffffffu, p, o);
        if (lane == 0) sc[wl][j] = p * 0.125f;   // /sqrt(64)
    }
    __syncwarp();
    float v0 = (lane < TT) ? sc[wl][lane] : -1e30f;
    float v1 = (lane + 32 < TT) ? sc[wl][lane + 32] : -1e30f;
    float mx = fmaxf(v0, v1);
#pragma unroll
    for (int o = 16; o; o >>= 1) mx = fmaxf(mx, __shfl_xor_sync(0xffffffffu, mx, o));
    float e0 = (lane < TT) ? expf(v0 - mx) : 0.f;
    float e1 = (lane + 32 < TT) ? expf(v1 - mx) : 0.f;
    float s = e0 + e1;
#pragma unroll
    for (int o = 16; o; o >>= 1) s += __shfl_xor_sync(0xffffffffu, s, o);
    float inv = 1.0f / s;
    if (lane < TT) sc[wl][lane] = e0 * inv;
    if (lane + 32 < TT) sc[wl][lane + 32] = e1 * inv;
    __syncwarp();
    float a0 = 0.f, a1 = 0.f;
    for (int j = 0; j < TT; j++) {
        float wj = sc[wl][j];
        const float* vp = base + j * 384 + 256 + h * 64;
        a0 += wj * vp[lane];
        a1 += wj * vp[lane + 32];
    }
    olast[b * HH + h * 64 + lane] = a0;
    olast[b * HH + h * 64 + lane + 32] = a1;
}

// ---------------- final: out-proj (last row) + MLP head ----------------
__global__ __launch_bounds__(128) void head_kernel(const float* __restrict__ olast,
                            const float* __restrict__ Wout, const float* __restrict__ bout,
                            const float* __restrict__ W1, const float* __restrict__ b1,
                            const float* __restrict__ W2, const float* __restrict__ b2,
                            float* __restrict__ pred) {
    int b = blockIdx.x;
    int j = threadIdx.x;  // 128
    __shared__ float o[HH], a[HH], hid[64];
    o[j] = olast[b * HH + j];
    __syncthreads();
    {
        float acc = bout[j];
        const float* w = Wout + (size_t)j * HH;
#pragma unroll 4
        for (int k = 0; k < HH; k++) acc += o[k] * w[k];
        a[j] = acc;
    }
    __syncthreads();
    if (j < 64) {
        float acc = b1[j];
        const float* w = W1 + (size_t)j * HH;
#pragma unroll 4
        for (int k = 0; k < HH; k++) acc += a[k] * w[k];
        hid[j] = fmaxf(acc, 0.0f);
    }
    __syncthreads();
    if (j == 0) {
        float p = b2[0];
#pragma unroll
        for (int k = 0; k < 64; k++) p += hid[k] * W2[k];
        pred[b] = p;
    }
}

// ---------------- host launch ----------------
extern "C" void kernel_launch(void* const* d_in, const int* in_sizes, int n_in,
                              void* d_out, int out_size) {
    (void)in_sizes; (void)n_in; (void)out_size;
    const float* x     = (const float*)d_in[0];
    const int*   eidx  = (const int*)d_in[1];
    const float* tseq  = (const float*)d_in[2];
    const float* W_red = (const float*)d_in[3];
    const float* b_red = (const float*)d_in[4];
    const float* s1Wl  = (const float*)d_in[5];
    const float* s1bl  = (const float*)d_in[6];
    const float* s1Wr  = (const float*)d_in[7];
    const float* s2Wl  = (const float*)d_in[8];
    const float* s2bl  = (const float*)d_in[9];
    const float* s2Wr  = (const float*)d_in[10];
    const float* Wih0  = (const float*)d_in[11];
    const float* Whh0  = (const float*)d_in[12];
    const float* bih0  = (const float*)d_in[13];
    const float* bhh0  = (const float*)d_in[14];
    const float* Wih1  = (const float*)d_in[15];
    const float* Whh1  = (const float*)d_in[16];
    const float* bih1  = (const float*)d_in[17];
    const float* bhh1  = (const float*)d_in[18];
    const float* Win   = (const float*)d_in[19];
    const float* binp  = (const float*)d_in[20];
    const float* Wout  = (const float*)d_in[21];
    const float* bout  = (const float*)d_in[22];
    const float* hW1   = (const float*)d_in[23];
    const float* hb1   = (const float*)d_in[24];
    const float* hW2   = (const float*)d_in[25];
    const float* hb2   = (const float*)d_in[26];

    float* out     = (float*)d_out;
    float* pred    = out;        // (64,1)
    float* spatial = out + BB;   // (50000,128)

    const int* src = eidx;
    const int* dst = eidx + EE;

    void* p;
    cudaGetSymbolAddress(&p, g_reduced); float* reduced = (float*)p;
    cudaGetSymbolAddress(&p, g_agg);     float* aggA    = (float*)p;
    cudaGetSymbolAddress(&p, g_aggB);    float* aggB    = (float*)p;
    cudaGetSymbolAddress(&p, g_tmp);     float* tmp     = (float*)p;
    cudaGetSymbolAddress(&p, g_invdeg);  float* invdeg  = (float*)p;
    cudaGetSymbolAddress(&p, g_deg);     int*   deg     = (int*)p;
    cudaGetSymbolAddress(&p, g_s);       float* sbuf    = (float*)p;
    cudaGetSymbolAddress(&p, g_ts);      float* ts      = (float*)p;
    cudaGetSymbolAddress(&p, g_gates);   float* gates   = (float*)p;
    cudaGetSymbolAddress(&p, g_h1);      float* h1      = (float*)p;
    cudaGetSymbolAddress(&p, g_h2);      float* h2      = (float*)p;
    cudaGetSymbolAddress(&p, g_qkv);     float* qkv     = (float*)p;
    cudaGetSymbolAddress(&p, g_olast);   float* olast   = (float*)p;
    cudaGetSymbolAddress(&p, g_WhhT0);   float* WhhT0   = (float*)p;
    cudaGetSymbolAddress(&p, g_WhhT1);   float* WhhT1   = (float*)p;

    static cudaStream_t s2 = nullptr, s4 = nullptr;
    static cudaEvent_t evFork = nullptr, evJoin = nullptr;
    static cudaEvent_t evRed = nullptr, evT1 = nullptr, evSage1 = nullptr, evT2 = nullptr;
    if (!s2) {
        cudaStreamCreateWithFlags(&s2, cudaStreamNonBlocking);
        cudaStreamCreateWithFlags(&s4, cudaStreamNonBlocking);
        cudaEventCreateWithFlags(&evFork, cudaEventDisableTiming);
        cudaEventCreateWithFlags(&evJoin, cudaEventDisableTiming);
        cudaEventCreateWithFlags(&evRed, cudaEventDisableTiming);
        cudaEventCreateWithFlags(&evT1, cudaEventDisableTiming);
        cudaEventCreateWithFlags(&evSage1, cudaEventDisableTiming);
        cudaEventCreateWithFlags(&evT2, cudaEventDisableTiming);
        cudaFuncSetAttribute(lstm_rec_kernel, cudaFuncAttributeMaxDynamicSharedMemorySize, LSTM_SMEM);
    }

    const dim3 gridBig((NND + 127) / 128, 1);

    // ===== fork =====
    cudaEventRecord(evFork, 0);
    cudaStreamWaitEvent(s2, evFork, 0);
    cudaStreamWaitEvent(s4, evFork, 0);

    // ---- temporal branch (stream s2) ----
    transposeW_kernel<<<256, 256, 0, s2>>>(Whh0, Whh1, WhhT0, WhhT1);
    gemm_tf32_kernel<<<dim3((BB * TT + 127) / 128, 1), 256, 0, s2>>>(
        tseq, W_red, tseq, W_red, nullptr, b_red, nullptr, ts, BB * TT, HH, FF, FF, 0);
    gemm_tf32_kernel<<<dim3((BB * TT + 127) / 128, 4), 256, 0, s2>>>(
        ts, Wih0, ts, Wih0, nullptr, bih0, nullptr, gates, BB * TT, 4 * HH, HH, HH, 0);
    lstm_rec_kernel<<<BB, 512, LSTM_SMEM, s2>>>(gates, WhhT0, bhh0, h1);
    gemm_tf32_kernel<<<dim3((BB * TT + 127) / 128, 4), 256, 0, s2>>>(
        h1, Wih1, h1, Wih1, nullptr, bih1, nullptr, gates, BB * TT, 4 * HH, HH, HH, 0);
    lstm_rec_kernel<<<BB, 512, LSTM_SMEM, s2>>>(gates, WhhT1, bhh1, h2);
    gemm_tf32_kernel<<<dim3((BB * TT + 127) / 128, 3), 256, 0, s2>>>(
        h2, Win, h2, Win, nullptr, binp, nullptr, qkv, BB * TT, 3 * HH, HH, HH, 0);
    attn_last_kernel<<<16, 256, 0, s2>>>(qkv, olast);
    head_kernel<<<BB, HH, 0, s2>>>(olast, Wout, bout, hW1, hb1, hW2, hb2, pred);

    // ---- s4: aggB memset + degree chain (all off the critical path) ----
    cudaMemsetAsync(aggB, 0, sizeof(float) * (size_t)NND * HH, s4);
    cudaMemsetAsync(deg, 0, sizeof(int) * NND, s4);
    deg_kernel<<<(EE + 255) / 256, 256, 0, s4>>>(dst, deg, EE);
    invdeg_kernel<<<(NND + 255) / 256, 256, 0, s4>>>(deg, invdeg, NND);

    // ---- graph branch (capture stream 0) ----
    cudaMemsetAsync(aggA, 0, sizeof(float) * (size_t)NND * HH);

    // reduced = x @ W_red^T + b_red
    gemm_tf32_kernel<<<gridBig, 256>>>(
        x, W_red, x, W_red, nullptr, b_red, nullptr, reduced, NND, HH, FF, FF, 0);
    cudaEventRecord(evRed, 0);

    // s4: tmp = reduced @ Wr1^T + bl1   (overlaps scatter1; also orders after invdeg)
    cudaStreamWaitEvent(s4, evRed, 0);
    gemm_tf32_kernel<<<gridBig, 256, 0, s4>>>(
        reduced, s1Wr, reduced, s1Wr, nullptr, s1bl, nullptr, tmp, NND, HH, HH, HH, 0);
    cudaEventRecord(evT1, s4);

    // stream 0: aggA += reduced[src] scattered to dst
    {
        long long tot = (long long)EE * 32;
        scatter_add_kernel<<<(unsigned)((tot + 255) / 256), 256>>>(reduced, src, dst, aggA, EE);
    }

    // sage1 = relu((aggA*invdeg) @ Wl1^T + tmp)   (evT1 also carries invdeg readiness)
    cudaStreamWaitEvent(0, evT1, 0);
    gemm_tf32_kernel<<<gridBig, 256>>>(
        aggA, s1Wl, aggA, s1Wl, invdeg, nullptr, tmp, sbuf, NND, HH, HH, HH, 1);
    cudaEventRecord(evSage1, 0);

    // s4: tmp = sbuf @ Wr2^T + bl2   (overlaps scatter2)
    cudaStreamWaitEvent(s4, evSage1, 0);
    gemm_tf32_kernel<<<gridBig, 256, 0, s4>>>(
        sbuf, s2Wr, sbuf, s2Wr, nullptr, s2bl, nullptr, tmp, NND, HH, HH, HH, 0);
    cudaEventRecord(evT2, s4);

    // stream 0: aggB += sbuf[src] scattered to dst
    {
        long long tot = (long long)EE * 32;
        scatter_add_kernel<<<(unsigned)((tot + 255) / 256), 256>>>(sbuf, src, dst, aggB, EE);
    }

    // spatial = relu((aggB*invdeg) @ Wl2^T + tmp)
    cudaStreamWaitEvent(0, evT2, 0);
    gemm_tf32_kernel<<<gridBig, 256>>>(
        aggB, s2Wl, aggB, s2Wl, invdeg, nullptr, tmp, spatial, NND, HH, HH, HH, 1);

    // ===== join =====
    cudaEventRecord(evJoin, s2);
    cudaStreamWaitEvent(0, evJoin, 0);
}

// round 15
// speedup vs baseline: 1.0781x; 1.0781x over previous
#include <cuda_runtime.h>
#include <cuda_bf16.h>
#include <math.h>
#include <stdint.h>

// Problem constants
#define NND 50000
#define FF  256
#define HH  128
#define EE  800000
#define BB  64
#define TT  50

// ---------------- device scratch ----------------
__device__ float g_reduced[NND * HH];
__device__ float g_agg[NND * HH];
__device__ float g_aggB[NND * HH];
__device__ float g_s[NND * HH];
__device__ float g_invdeg[NND];
__device__ int   g_deg[NND];
__device__ float g_ts[BB * TT * HH];
__device__ float g_gates[BB * TT * 4 * HH];
__device__ float g_h1[BB * TT * HH];
__device__ float g_h2[BB * TT * HH];
__device__ float g_qkv[BB * TT * 3 * HH];
__device__ float g_olast[BB * HH];
__device__ float g_WhhT0[HH * 4 * HH];   // [128][512] transposed fp32 Whh0
__device__ float g_WhhT1[HH * 4 * HH];   // [128][512] transposed fp32 Whh1

__device__ __forceinline__ float sigf(float x) { return 1.0f / (1.0f + __expf(-x)); }
// tanh(x) = 1 - 2/(exp(2x)+1)  -> MUFU.EX2 + MUFU.RCP
__device__ __forceinline__ float tanh_e(float x) { return 1.0f - 2.0f / (__expf(2.0f * x) + 1.0f); }

__device__ __forceinline__ uint32_t f2tf32(float f) {
    uint32_t u;
    asm("cvt.rna.tf32.f32 %0, %1;" : "=r"(u) : "f"(f));
    return u;
}

__device__ __forceinline__ void mma_tf32(float* d, const uint32_t* a, const uint32_t* b) {
    asm volatile("mma.sync.aligned.m16n8k8.row.col.f32.tf32.tf32.f32 "
                 "{%0,%1,%2,%3}, {%4,%5,%6,%7}, {%8,%9}, {%0,%1,%2,%3};"
                 : "+f"(d[0]), "+f"(d[1]), "+f"(d[2]), "+f"(d[3])
                 : "r"(a[0]), "r"(a[1]), "r"(a[2]), "r"(a[3]), "r"(b[0]), "r"(b[1]));
}

// ---------------- degree kernels ----------------
__global__ __launch_bounds__(256) void deg_kernel(const int* __restrict__ dst, int* __restrict__ deg, int E) {
    int i = blockIdx.x * blockDim.x + threadIdx.x;
    if (i < E) atomicAdd(&deg[dst[i]], 1);
}

__global__ __launch_bounds__(256) void invdeg_kernel(const int* __restrict__ deg, float* __restrict__ inv, int n) {
    int i = blockIdx.x * blockDim.x + threadIdx.x;
    if (i < n) inv[i] = 1.0f / (float)max(deg[i], 1);
}

// ---------------- weight transpose: Whh[512][128] -> WhhT[128][512], fp32 ----------------
__global__ __launch_bounds__(256) void transposeW_kernel(const float* __restrict__ W0,
                                                         const float* __restrict__ W1,
                                                         float* __restrict__ T0,
                                                         float* __restrict__ T1) {
    int idx = blockIdx.x * blockDim.x + threadIdx.x;
    if (idx < 512 * 128) {
        int j = idx >> 7;      // gate row 0..511
        int k = idx & 127;     // hidden col 0..127
        T0[k * 512 + j] = W0[idx];
        T1[k * 512 + j] = W1[idx];
    }
}

// ---------------- scatter-add (one warp per edge, v4 reductions) ----------------
__global__ __launch_bounds__(256) void scatter_add_kernel(const float* __restrict__ feat,
                                   const int* __restrict__ src,
                                   const int* __restrict__ dst,
                                   float* __restrict__ agg, int E) {
    int idx = blockIdx.x * blockDim.x + threadIdx.x;
    int e = idx >> 5;
    if (e >= E) return;
    int lane = idx & 31;
    int s = __ldg(src + e);
    int d = __ldg(dst + e);
    float4 v = *(const float4*)(feat + (size_t)s * HH + lane * 4);
    float* p = agg + (size_t)d * HH + lane * 4;
    asm volatile("red.global.add.v4.f32 [%0], {%1,%2,%3,%4};"
                 :: "l"(p), "f"(v.x), "f"(v.y), "f"(v.z), "f"(v.w) : "memory");
}

// ---------------- tf32 tensor-core NT GEMM (R11 loop) ----------------
// C = A1@B1^T (+A2@B2^T) + bias, optional relu, optional rowscale on A1 rows.
#define KT 16
__global__ __launch_bounds__(256) void gemm_tf32_kernel(
        const float* __restrict__ A1, const float* __restrict__ B1,
        const float* __restrict__ A2, const float* __restrict__ B2,
        const float* __restrict__ rowscale,
        const float* __restrict__ bias,
        float* __restrict__ C,
        int M, int N, int Ktot, int Ksplit, int relu) {
    __shared__ uint32_t As[2][KT][136];
    __shared__ uint32_t Bs[2][KT][136];
    const int tid  = threadIdx.x;
    const int m0   = blockIdx.x * 128;
    const int n0   = blockIdx.y * 128;
    const int warp = tid >> 5, lane = tid & 31;
    const int wm   = (warp >> 1) * 32;   // 4 warps in m
    const int wn   = (warp & 1) * 64;    // 2 warps in n
    const int g    = lane >> 2, c = lane & 3;
    const bool haveScale = (rowscale != nullptr);

    float acc[2][8][4];
#pragma unroll
    for (int mt = 0; mt < 2; mt++)
#pragma unroll
        for (int nt = 0; nt < 8; nt++)
#pragma unroll
            for (int r = 0; r < 4; r++) acc[mt][nt][r] = 0.0f;

    const int numSlabs = Ktot / KT;

    const int row0 = tid & 127, kc0 = tid >> 7;          // kc0 in {0,1}
    const int row1 = tid & 127, kc1 = (tid >> 7) + 2;    // {2,3}

    float4 pa[2], pb[2];

    auto loadSlab = [&](int s) {
        int kbase = s * KT;
        const float* A; const float* Bm; int lda, koff; bool sc;
        if (kbase < Ksplit) { A = A1; Bm = B1; lda = Ksplit;        koff = kbase;          sc = haveScale; }
        else                { A = A2; Bm = B2; lda = Ktot - Ksplit; koff = kbase - Ksplit; sc = false; }
        {
            int m = m0 + row0;
            pa[0] = make_float4(0.f, 0.f, 0.f, 0.f);
            if (m < M) {
                pa[0] = *(const float4*)(A + (size_t)m * lda + koff + kc0 * 4);
                if (sc) { float sv = rowscale[m]; pa[0].x *= sv; pa[0].y *= sv; pa[0].z *= sv; pa[0].w *= sv; }
            }
            pb[0] = *(const float4*)(Bm + (size_t)(n0 + row0) * lda + koff + kc0 * 4);
        }
        {
            int m = m0 + row1;
            pa[1] = make_float4(0.f, 0.f, 0.f, 0.f);
            if (m < M) {
                pa[1] = *(const float4*)(A + (size_t)m * lda + koff + kc1 * 4);
                if (sc) { float sv = rowscale[m]; pa[1].x *= sv; pa[1].y *= sv; pa[1].z *= sv; pa[1].w *= sv; }
            }
            pb[1] = *(const float4*)(Bm + (size_t)(n0 + row1) * lda + koff + kc1 * 4);
        }
    };

    auto storeSlab = [&](int buf) {
        int k0 = kc0 * 4;
        As[buf][k0 + 0][row0] = f2tf32(pa[0].x); As[buf][k0 + 1][row0] = f2tf32(pa[0].y);
        As[buf][k0 + 2][row0] = f2tf32(pa[0].z); As[buf][k0 + 3][row0] = f2tf32(pa[0].w);
        Bs[buf][k0 + 0][row0] = f2tf32(pb[0].x); Bs[buf][k0 + 1][row0] = f2tf32(pb[0].y);
        Bs[buf][k0 + 2][row0] = f2tf32(pb[0].z); Bs[buf][k0 + 3][row0] = f2tf32(pb[0].w);
        int k1 = kc1 * 4;
        As[buf][k1 + 0][row1] = f2tf32(pa[1].x); As[buf][k1 + 1][row1] = f2tf32(pa[1].y);
        As[buf][k1 + 2][row1] = f2tf32(pa[1].z); As[buf][k1 + 3][row1] = f2tf32(pa[1].w);
        Bs[buf][k1 + 0][row1] = f2tf32(pb[1].x); Bs[buf][k1 + 1][row1] = f2tf32(pb[1].y);
        Bs[buf][k1 + 2][row1] = f2tf32(pb[1].z); Bs[buf][k1 + 3][row1] = f2tf32(pb[1].w);
    };

    loadSlab(0);
    storeSlab(0);
    __syncthreads();

    for (int s = 0; s < numSlabs; s++) {
        int cur = s & 1;
        bool more = (s + 1) < numSlabs;
        if (more) loadSlab(s + 1);
#pragma unroll
        for (int k8 = 0; k8 < 2; k8++) {
            int kb = k8 * 8;
            uint32_t afr[2][4], bfr[8][2];
#pragma unroll
            for (int mt = 0; mt < 2; mt++) {
                int mb = wm + mt * 16 + g;
                afr[mt][0] = As[cur][kb + c][mb];
                afr[mt][1] = As[cur][kb + c][mb + 8];
                afr[mt][2] = As[cur][kb + c + 4][mb];
                afr[mt][3] = As[cur][kb + c + 4][mb + 8];
            }
#pragma unroll
            for (int nt = 0; nt < 8; nt++) {
                int nb = wn + nt * 8 + g;
                bfr[nt][0] = Bs[cur][kb + c][nb];
                bfr[nt][1] = Bs[cur][kb + c + 4][nb];
            }
#pragma unroll
            for (int mt = 0; mt < 2; mt++)
#pragma unroll
                for (int nt = 0; nt < 8; nt++)
                    mma_tf32(acc[mt][nt], afr[mt], bfr[nt]);
        }
        __syncthreads();
        if (more) {
            storeSlab(1 - cur);
            __syncthreads();
        }
    }

    // epilogue
#pragma unroll
    for (int mt = 0; mt < 2; mt++) {
#pragma unroll
        for (int nt = 0; nt < 8; nt++) {
            const float* d = acc[mt][nt];
            int mrow = m0 + wm + mt * 16 + g;
            int ncol = n0 + wn + nt * 8 + 2 * c;
            float b0v = 0.f, b1v = 0.f;
            if (bias) { b0v = bias[ncol]; b1v = bias[ncol + 1]; }
            float v0 = d[0] + b0v, v1 = d[1] + b1v;
            float v2 = d[2] + b0v, v3 = d[3] + b1v;
            if (relu) {
                v0 = fmaxf(v0, 0.f); v1 = fmaxf(v1, 0.f);
                v2 = fmaxf(v2, 0.f); v3 = fmaxf(v3, 0.f);
            }
            if (mrow < M)     *(float2*)(C + (size_t)mrow * N + ncol)       = make_float2(v0, v1);
            if (mrow + 8 < M) *(float2*)(C + (size_t)(mrow + 8) * N + ncol) = make_float2(v2, v3);
        }
    }
}

// ---------------- LSTM recurrence: fp32 smem weights, R10 scalar-h form ----------------
#define SW_K 112
#define KREM (HH - SW_K)   // 16
#define LSTM_SMEM (SW_K * 512 * 4 + HH * 4 + 4 * HH * 4)   // 231936 bytes
__global__ __launch_bounds__(512) void lstm_rec_kernel(
                                const float* __restrict__ gx,    // B*T*512 = x@Wih^T + bih
                                const float* __restrict__ WhhT,  // [128][512] fp32
                                const float* __restrict__ bhh,   // [512]
                                float* __restrict__ hout) {      // B*T*128
    extern __shared__ float smemf[];
    float* sw   = smemf;                  // [SW_K][512]
    float* sh_h = smemf + SW_K * 512;     // [128]
    float* sh_g = sh_h + HH;              // [512]
    const int b = blockIdx.x;
    const int j = threadIdx.x;            // 0..511

    for (int idx = j; idx < SW_K * 512; idx += 512) sw[idx] = WhhT[idx];
    const float bh = __ldg(bhh + j);
    float cstate = 0.0f;
    if (j < HH) sh_h[j] = 0.0f;
    __syncthreads();

    const float* gbase = gx + (size_t)b * TT * 512;
    const float* wrem_base = WhhT + SW_K * 512;
    for (int t = 0; t < TT; t++) {
        float acc = gbase[t * 512 + j] + bh;
        float wrem[KREM];
#pragma unroll
        for (int i = 0; i < KREM; i++)
            wrem[i] = __ldg(wrem_base + i * 512 + j);   // L2, prefetched (MLP=16)
#pragma unroll 16
        for (int k = 0; k < SW_K; k++)
            acc += sw[k * 512 + j] * sh_h[k];
#pragma unroll
        for (int i = 0; i < KREM; i++)
            acc += wrem[i] * sh_h[SW_K + i];
        sh_g[j] = acc;
        __syncthreads();
        if (j < HH) {
            float gi = sh_g[j], gf = sh_g[HH + j], gg = sh_g[2 * HH + j], go = sh_g[3 * HH + j];
            cstate = sigf(gf) * cstate + sigf(gi) * tanh_e(gg);
            float h = sigf(go) * tanh_e(cstate);
            sh_h[j] = h;
            hout[((size_t)b * TT + t) * HH + j] = h;
        }
        __syncthreads();
    }
}

// ---------------- attention: only last query row needed ----------------
__global__ __launch_bounds__(256) void attn_last_kernel(const float* __restrict__ qkv, float* __restrict__ olast) {
    int gidx = blockIdx.x * blockDim.x + threadIdx.x;
    int w = gidx >> 5;                // 0..127 : (b, head)
    if (w >= BB * 2) return;
    int lane = threadIdx.x & 31;
    int wl = threadIdx.x >> 5;
    int b = w >> 1, h = w & 1;
    const float* base = qkv + (size_t)b * TT * 384;
    const float* q = base + 49 * 384 + h * 64;
    float q0 = q[lane], q1 = q[lane + 32];
    __shared__ float sc[8][TT];
    for (int j = 0; j < TT; j++) {
        const float* kp = base + j * 384 + 128 + h * 64;
        float p = q0 * kp[lane] + q1 * kp[lane + 32];
#pragma unroll
        for (int o = 16; o; o >>= 1) p += __shfl_down_sync(0xffffffffu, p, o);
        if (lane == 0) sc[wl][j] = p * 0.125f;   // /sqrt(64)
    }
    __syncwarp();
    float v0 = (lane < TT) ? sc[wl][lane] : -1e30f;
    float v1 = (lane + 32 < TT) ? sc[wl][lane + 32] : -1e30f;
    float mx = fmaxf(v0, v1);
#pragma unroll
    for (int o = 16; o; o >>= 1) mx = fmaxf(mx, __shfl_xor_sync(0xffffffffu, mx, o));
    float e0 = (lane < TT) ? expf(v0 - mx) : 0.f;
    float e1 = (lane + 32 < TT) ? expf(v1 - mx) : 0.f;
    float s = e0 + e1;
#pragma unroll
    for (int o = 16; o; o >>= 1) s += __shfl_xor_sync(0xffffffffu, s, o);
    float inv = 1.0f / s;
    if (lane < TT) sc[wl][lane] = e0 * inv;
    if (lane + 32 < TT) sc[wl][lane + 32] = e1 * inv;
    __syncwarp();
    float a0 = 0.f, a1 = 0.f;
    for (int j = 0; j < TT; j++) {
        float wj = sc[wl][j];
        const float* vp = base + j * 384 + 256 + h * 64;
        a0 += wj * vp[lane];
        a1 += wj * vp[lane + 32];
    }
    olast[b * HH + h * 64 + lane] = a0;
    olast[b * HH + h * 64 + lane + 32] = a1;
}

// ---------------- final: out-proj (last row) + MLP head ----------------
__global__ __launch_bounds__(128) void head_kernel(const float* __restrict__ olast,
                            const float* __restrict__ Wout, const float* __restrict__ bout,
                            const float* __restrict__ W1, const float* __restrict__ b1,
                            const float* __restrict__ W2, const float* __restrict__ b2,
                            float* __restrict__ pred) {
    int b = blockIdx.x;
    int j = threadIdx.x;  // 128
    __shared__ float o[HH], a[HH], hid[64];
    o[j] = olast[b * HH + j];
    __syncthreads();
    {
        float acc = bout[j];
        const float* w = Wout + (size_t)j * HH;
#pragma unroll 4
        for (int k = 0; k < HH; k++) acc += o[k] * w[k];
        a[j] = acc;
    }
    __syncthreads();
    if (j < 64) {
        float acc = b1[j];
        const float* w = W1 + (size_t)j * HH;
#pragma unroll 4
        for (int k = 0; k < HH; k++) acc += a[k] * w[k];
        hid[j] = fmaxf(acc, 0.0f);
    }
    __syncthreads();
    if (j == 0) {
        float p = b2[0];
#pragma unroll
        for (int k = 0; k < 64; k++) p += hid[k] * W2[k];
        pred[b] = p;
    }
}

// ---------------- host launch ----------------
extern "C" void kernel_launch(void* const* d_in, const int* in_sizes, int n_in,
                              void* d_out, int out_size) {
    (void)in_sizes; (void)n_in; (void)out_size;
    const float* x     = (const float*)d_in[0];
    const int*   eidx  = (const int*)d_in[1];
    const float* tseq  = (const float*)d_in[2];
    const float* W_red = (const float*)d_in[3];
    const float* b_red = (const float*)d_in[4];
    const float* s1Wl  = (const float*)d_in[5];
    const float* s1bl  = (const float*)d_in[6];
    const float* s1Wr  = (const float*)d_in[7];
    const float* s2Wl  = (const float*)d_in[8];
    const float* s2bl  = (const float*)d_in[9];
    const float* s2Wr  = (const float*)d_in[10];
    const float* Wih0  = (const float*)d_in[11];
    const float* Whh0  = (const float*)d_in[12];
    const float* bih0  = (const float*)d_in[13];
    const float* bhh0  = (const float*)d_in[14];
    const float* Wih1  = (const float*)d_in[15];
    const float* Whh1  = (const float*)d_in[16];
    const float* bih1  = (const float*)d_in[17];
    const float* bhh1  = (const float*)d_in[18];
    const float* Win   = (const float*)d_in[19];
    const float* binp  = (const float*)d_in[20];
    const float* Wout  = (const float*)d_in[21];
    const float* bout  = (const float*)d_in[22];
    const float* hW1   = (const float*)d_in[23];
    const float* hb1   = (const float*)d_in[24];
    const float* hW2   = (const float*)d_in[25];
    const float* hb2   = (const float*)d_in[26];

    float* out     = (float*)d_out;
    float* pred    = out;        // (64,1)
    float* spatial = out + BB;   // (50000,128)

    const int* src = eidx;
    const int* dst = eidx + EE;

    void* p;
    cudaGetSymbolAddress(&p, g_reduced); float* reduced = (float*)p;
    cudaGetSymbolAddress(&p, g_agg);     float* aggA    = (float*)p;
    cudaGetSymbolAddress(&p, g_aggB);    float* aggB    = (float*)p;
    cudaGetSymbolAddress(&p, g_invdeg);  float* invdeg  = (float*)p;
    cudaGetSymbolAddress(&p, g_deg);     int*   deg     = (int*)p;
    cudaGetSymbolAddress(&p, g_s);       float* sbuf    = (float*)p;
    cudaGetSymbolAddress(&p, g_ts);      float* ts      = (float*)p;
    cudaGetSymbolAddress(&p, g_gates);   float* gates   = (float*)p;
    cudaGetSymbolAddress(&p, g_h1);      float* h1      = (float*)p;
    cudaGetSymbolAddress(&p, g_h2);      float* h2      = (float*)p;
    cudaGetSymbolAddress(&p, g_qkv);     float* qkv     = (float*)p;
    cudaGetSymbolAddress(&p, g_olast);   float* olast   = (float*)p;
    cudaGetSymbolAddress(&p, g_WhhT0);   float* WhhT0   = (float*)p;
    cudaGetSymbolAddress(&p, g_WhhT1);   float* WhhT1   = (float*)p;

    static cudaStream_t s2 = nullptr, s4 = nullptr;
    static cudaEvent_t evFork = nullptr, evJoin = nullptr, evDeg = nullptr;
    if (!s2) {
        cudaStreamCreateWithFlags(&s2, cudaStreamNonBlocking);
        cudaStreamCreateWithFlags(&s4, cudaStreamNonBlocking);
        cudaEventCreateWithFlags(&evFork, cudaEventDisableTiming);
        cudaEventCreateWithFlags(&evJoin, cudaEventDisableTiming);
        cudaEventCreateWithFlags(&evDeg, cudaEventDisableTiming);
        cudaFuncSetAttribute(lstm_rec_kernel, cudaFuncAttributeMaxDynamicSharedMemorySize, LSTM_SMEM);
    }

    const dim3 gridBig((NND + 127) / 128, 1);

    // ===== fork =====
    cudaEventRecord(evFork, 0);
    cudaStreamWaitEvent(s2, evFork, 0);
    cudaStreamWaitEvent(s4, evFork, 0);

    // ---- temporal branch (stream s2) ----
    transposeW_kernel<<<256, 256, 0, s2>>>(Whh0, Whh1, WhhT0, WhhT1);
    gemm_tf32_kernel<<<dim3((BB * TT + 127) / 128, 1), 256, 0, s2>>>(
        tseq, W_red, tseq, W_red, nullptr, b_red, ts, BB * TT, HH, FF, FF, 0);
    gemm_tf32_kernel<<<dim3((BB * TT + 127) / 128, 4), 256, 0, s2>>>(
        ts, Wih0, ts, Wih0, nullptr, bih0, gates, BB * TT, 4 * HH, HH, HH, 0);
    lstm_rec_kernel<<<BB, 512, LSTM_SMEM, s2>>>(gates, WhhT0, bhh0, h1);
    gemm_tf32_kernel<<<dim3((BB * TT + 127) / 128, 4), 256, 0, s2>>>(
        h1, Wih1, h1, Wih1, nullptr, bih1, gates, BB * TT, 4 * HH, HH, HH, 0);
    lstm_rec_kernel<<<BB, 512, LSTM_SMEM, s2>>>(gates, WhhT1, bhh1, h2);
    gemm_tf32_kernel<<<dim3((BB * TT + 127) / 128, 3), 256, 0, s2>>>(
        h2, Win, h2, Win, nullptr, binp, qkv, BB * TT, 3 * HH, HH, HH, 0);
    attn_last_kernel<<<16, 256, 0, s2>>>(qkv, olast);
    head_kernel<<<BB, HH, 0, s2>>>(olast, Wout, bout, hW1, hb1, hW2, hb2, pred);

    // ---- s4: aggB memset + degree chain (off the critical path) ----
    cudaMemsetAsync(aggB, 0, sizeof(float) * (size_t)NND * HH, s4);
    cudaMemsetAsync(deg, 0, sizeof(int) * NND, s4);
    deg_kernel<<<(EE + 255) / 256, 256, 0, s4>>>(dst, deg, EE);
    invdeg_kernel<<<(NND + 255) / 256, 256, 0, s4>>>(deg, invdeg, NND);
    cudaEventRecord(evDeg, s4);

    // ---- graph branch (capture stream 0, R11 structure) ----
    cudaMemsetAsync(aggA, 0, sizeof(float) * (size_t)NND * HH);

    // reduced = x @ W_red^T + b_red
    gemm_tf32_kernel<<<gridBig, 256>>>(
        x, W_red, x, W_red, nullptr, b_red, reduced, NND, HH, FF, FF, 0);

    // aggA += reduced[src] scattered to dst
    {
        long long tot = (long long)EE * 32;
        scatter_add_kernel<<<(unsigned)((tot + 255) / 256), 256>>>(reduced, src, dst, aggA, EE);
    }

    // join degree chain before sage1 (needs invdeg)
    cudaStreamWaitEvent(0, evDeg, 0);

    // sage1 = relu((aggA*invdeg) @ Wl1^T + bl1 + reduced @ Wr1^T)   (fused K=256)
    gemm_tf32_kernel<<<gridBig, 256>>>(
        aggA, s1Wl, reduced, s1Wr, invdeg, s1bl, sbuf, NND, HH, 2 * HH, HH, 1);

    // aggB += sbuf[src] scattered to dst   (aggB pre-zeroed on s4, ordered by evDeg)
    {
        long long tot = (long long)EE * 32;
        scatter_add_kernel<<<(unsigned)((tot + 255) / 256), 256>>>(sbuf, src, dst, aggB, EE);
    }

    // spatial = relu((aggB*invdeg) @ Wl2^T + bl2 + sbuf @ Wr2^T)   (fused K=256)
    gemm_tf32_kernel<<<gridBig, 256>>>(
        aggB, s2Wl, sbuf, s2Wr, invdeg, s2bl, spatial, NND, HH, 2 * HH, HH, 1);

    // ===== join =====
    cudaEventRecord(evJoin, s2);
    cudaStreamWaitEvent(0, evJoin, 0);
}